// round 2
// baseline (speedup 1.0000x reference)
#include <cuda_runtime.h>
#include <cuda_fp16.h>

#define DD 64
#define TT 512
#define BBATCH 1024
#define ROWS_PER_CTA 8
#define NCTA (BBATCH / ROWS_PER_CTA)   /* 128 */
#define NTHREADS 256

// All weights live in SMEM as fp16 (k-interleaved half2), states fp32.
struct SmemLayout {
    __half2 Wff[3][32][64];   // W_from_W, W_from_I, W_from_A
    __half2 Wg[2][32][64];    // W_gate rows [I | A]
    __half2 Iz[3][32][64];    // I_z rows [Wn | I | A]
    __half2 Ir[3][32][64];
    __half2 Ih[3][32][64];    // h rows [Wn | r*I | A]
    __half2 Aff[3][32][64];   // A_from_W, A_from_I, A_from_A
    __half2 Agt[2][32][64];   // A_gate rows [Wn | In]
    float   w_enc[8][64];
    float   phi[64][4];
    float   b_enc[64], b_Wg[64], b_z[64], b_r[64], b_h[64], b_Ag[64], b_phi[4];
    float   sW[8][64], sI[8][64], sA[8][64], sRI[8][64];
    float   xs[8][8];
};

extern __shared__ char smem_raw[];

__device__ __forceinline__ float tanh_f(float x) {
    // accurate tanh via __expf (~1e-6 rel err); clamp avoids inf/inf
    x = fminf(fmaxf(x, -9.0f), 9.0f);
    float e = __expf(2.0f * x);
    return __fdividef(e - 1.0f, e + 1.0f);
}
__device__ __forceinline__ float sigm_f(float x) {
    return __fdividef(1.0f, 1.0f + __expf(-x));
}

// dot over K=64 for two rows sharing the same weight column j.
// w[p][j] holds (wt[2p][j], wt[2p+1][j]); state read as broadcast float4.
__device__ __forceinline__ float2 dot64_pair(const __half2 (&w)[32][64], int j,
                                             const float* __restrict__ s0,
                                             const float* __restrict__ s1) {
    float a0 = 0.f, b0 = 0.f, a1 = 0.f, b1 = 0.f;
#pragma unroll
    for (int q = 0; q < 16; q++) {
        float4 v0 = *reinterpret_cast<const float4*>(s0 + 4 * q);
        float4 v1 = *reinterpret_cast<const float4*>(s1 + 4 * q);
        float2 wa = __half22float2(w[2 * q][j]);
        float2 wb = __half22float2(w[2 * q + 1][j]);
        a0 = fmaf(v0.x, wa.x, a0); b0 = fmaf(v0.y, wa.y, b0);
        a0 = fmaf(v0.z, wb.x, a0); b0 = fmaf(v0.w, wb.y, b0);
        a1 = fmaf(v1.x, wa.x, a1); b1 = fmaf(v1.y, wa.y, b1);
        a1 = fmaf(v1.z, wb.x, a1); b1 = fmaf(v1.w, wb.y, b1);
    }
    return make_float2(a0 + b0, a1 + b1);
}

__device__ __forceinline__ void stage_chunk(__half2 (&dst)[32][64],
                                            const float* __restrict__ src) {
    for (int i = threadIdx.x; i < 2048; i += NTHREADS) {
        int p = i >> 6, jj = i & 63;
        dst[p][jj] = __floats2half2_rn(src[(2 * p) * 64 + jj],
                                       src[(2 * p + 1) * 64 + jj]);
    }
}

__global__ void __launch_bounds__(NTHREADS, 1)
anima_kernel(const float* __restrict__ x,
             const float* __restrict__ we_w, const float* __restrict__ we_b,
             const float* __restrict__ WfW, const float* __restrict__ WfI,
             const float* __restrict__ WfA,
             const float* __restrict__ Wg_w, const float* __restrict__ Wg_b,
             const float* __restrict__ Iz_w, const float* __restrict__ Iz_b,
             const float* __restrict__ Ir_w, const float* __restrict__ Ir_b,
             const float* __restrict__ Ih_w, const float* __restrict__ Ih_b,
             const float* __restrict__ AfW, const float* __restrict__ AfI,
             const float* __restrict__ AfA,
             const float* __restrict__ Ag_w, const float* __restrict__ Ag_b,
             const float* __restrict__ phi_w, const float* __restrict__ phi_b,
             float* __restrict__ out) {
    SmemLayout* S = reinterpret_cast<SmemLayout*>(smem_raw);
    const int tid = threadIdx.x;

    // ---- one-time weight staging (fp32 global -> fp16 smem, k-interleaved)
    stage_chunk(S->Wff[0], WfW);
    stage_chunk(S->Wff[1], WfI);
    stage_chunk(S->Wff[2], WfA);
    stage_chunk(S->Wg[0], Wg_w);
    stage_chunk(S->Wg[1], Wg_w + 64 * 64);
    stage_chunk(S->Iz[0], Iz_w);
    stage_chunk(S->Iz[1], Iz_w + 64 * 64);
    stage_chunk(S->Iz[2], Iz_w + 128 * 64);
    stage_chunk(S->Ir[0], Ir_w);
    stage_chunk(S->Ir[1], Ir_w + 64 * 64);
    stage_chunk(S->Ir[2], Ir_w + 128 * 64);
    stage_chunk(S->Ih[0], Ih_w);
    stage_chunk(S->Ih[1], Ih_w + 64 * 64);
    stage_chunk(S->Ih[2], Ih_w + 128 * 64);
    stage_chunk(S->Aff[0], AfW);
    stage_chunk(S->Aff[1], AfI);
    stage_chunk(S->Aff[2], AfA);
    stage_chunk(S->Agt[0], Ag_w);
    stage_chunk(S->Agt[1], Ag_w + 64 * 64);

    for (int i = tid; i < 8 * 64; i += NTHREADS)
        (&S->w_enc[0][0])[i] = we_w[i];
    for (int i = tid; i < 64 * 4; i += NTHREADS)
        (&S->phi[0][0])[i] = phi_w[i];
    for (int i = tid; i < 64; i += NTHREADS) {
        S->b_enc[i] = we_b[i];
        S->b_Wg[i] = Wg_b[i];
        S->b_z[i] = Iz_b[i];
        S->b_r[i] = Ir_b[i];
        S->b_h[i] = Ih_b[i];
        S->b_Ag[i] = Ag_b[i];
    }
    if (tid < 4) S->b_phi[tid] = phi_b[tid];
    for (int i = tid; i < 8 * 64; i += NTHREADS) {
        (&S->sW[0][0])[i] = 0.f;
        (&S->sI[0][0])[i] = 0.f;
        (&S->sA[0][0])[i] = 0.f;
        (&S->sRI[0][0])[i] = 0.f;
    }
    __syncthreads();

    const int j = tid & 63;
    const int g = tid >> 6;      // 0..3
    const int r0 = g, r1 = g + 4;
    const long base = (long)blockIdx.x * ROWS_PER_CTA;

    for (int t = 0; t < TT; t++) {
        // stage x_t for our 8 rows
        if (tid < 64) {
            int rr = tid >> 3, ss = tid & 7;
            S->xs[rr][ss] = x[(base + rr) * (TT * 8) + t * 8 + ss];
        }
        __syncthreads();

        // ---------------- Phase 1: xt, Wg, W_in -> W_new ----------------
        float e0 = S->b_enc[j], e1 = e0;
#pragma unroll
        for (int s = 0; s < 8; s++) {
            float wv = S->w_enc[s][j];
            e0 = fmaf(S->xs[r0][s], wv, e0);
            e1 = fmaf(S->xs[r1][s], wv, e1);
        }
        float xt0 = tanh_f(e0), xt1 = tanh_f(e1);

        float2 d;
        float gi0 = S->b_Wg[j], gi1 = gi0;
        d = dot64_pair(S->Wg[0], j, S->sI[r0], S->sI[r1]); gi0 += d.x; gi1 += d.y;
        d = dot64_pair(S->Wg[1], j, S->sA[r0], S->sA[r1]); gi0 += d.x; gi1 += d.y;
        float wg0 = sigm_f(gi0), wg1 = sigm_f(gi1);

        float wi0 = xt0, wi1 = xt1;
        d = dot64_pair(S->Wff[0], j, S->sW[r0], S->sW[r1]); wi0 += d.x; wi1 += d.y;
        d = dot64_pair(S->Wff[1], j, S->sI[r0], S->sI[r1]); wi0 += d.x; wi1 += d.y;
        d = dot64_pair(S->Wff[2], j, S->sA[r0], S->sA[r1]); wi0 += d.x; wi1 += d.y;
        float Wn0 = tanh_f(wi0) * wg0;
        float Wn1 = tanh_f(wi1) * wg1;

        __syncthreads();
        S->sW[r0][j] = Wn0; S->sW[r1][j] = Wn1;
        __syncthreads();

        // ---------------- Phase 2: z, r, r*I ----------------
        float z0 = S->b_z[j], z1 = z0;
        float q0 = S->b_r[j], q1 = q0;
        d = dot64_pair(S->Iz[0], j, S->sW[r0], S->sW[r1]); z0 += d.x; z1 += d.y;
        d = dot64_pair(S->Iz[1], j, S->sI[r0], S->sI[r1]); z0 += d.x; z1 += d.y;
        d = dot64_pair(S->Iz[2], j, S->sA[r0], S->sA[r1]); z0 += d.x; z1 += d.y;
        d = dot64_pair(S->Ir[0], j, S->sW[r0], S->sW[r1]); q0 += d.x; q1 += d.y;
        d = dot64_pair(S->Ir[1], j, S->sI[r0], S->sI[r1]); q0 += d.x; q1 += d.y;
        d = dot64_pair(S->Ir[2], j, S->sA[r0], S->sA[r1]); q0 += d.x; q1 += d.y;
        z0 = sigm_f(z0); z1 = sigm_f(z1);
        float rv0 = sigm_f(q0), rv1 = sigm_f(q1);
        float Iold0 = S->sI[r0][j], Iold1 = S->sI[r1][j];
        __syncthreads();
        S->sRI[r0][j] = rv0 * Iold0; S->sRI[r1][j] = rv1 * Iold1;
        __syncthreads();

        // ---------------- Phase 3: h, I_new ----------------
        float h0 = S->b_h[j], h1 = h0;
        d = dot64_pair(S->Ih[0], j, S->sW[r0], S->sW[r1]); h0 += d.x; h1 += d.y;
        d = dot64_pair(S->Ih[1], j, S->sRI[r0], S->sRI[r1]); h0 += d.x; h1 += d.y;
        d = dot64_pair(S->Ih[2], j, S->sA[r0], S->sA[r1]); h0 += d.x; h1 += d.y;
        h0 = tanh_f(h0); h1 = tanh_f(h1);
        float In0 = (1.f - z0) * Iold0 + z0 * h0;
        float In1 = (1.f - z1) * Iold1 + z1 * h1;
        __syncthreads();
        S->sI[r0][j] = In0; S->sI[r1][j] = In1;
        __syncthreads();

        // ---------------- Phase 4: Ag, A_in -> A_new ----------------
        float ga0 = S->b_Ag[j], ga1 = ga0;
        d = dot64_pair(S->Agt[0], j, S->sW[r0], S->sW[r1]); ga0 += d.x; ga1 += d.y;
        d = dot64_pair(S->Agt[1], j, S->sI[r0], S->sI[r1]); ga0 += d.x; ga1 += d.y;
        float ai0 = 0.f, ai1 = 0.f;
        d = dot64_pair(S->Aff[0], j, S->sW[r0], S->sW[r1]); ai0 += d.x; ai1 += d.y;
        d = dot64_pair(S->Aff[1], j, S->sI[r0], S->sI[r1]); ai0 += d.x; ai1 += d.y;
        d = dot64_pair(S->Aff[2], j, S->sA[r0], S->sA[r1]); ai0 += d.x; ai1 += d.y;
        float An0 = tanh_f(ai0) * sigm_f(ga0);
        float An1 = tanh_f(ai1) * sigm_f(ga1);
        __syncthreads();
        S->sA[r0][j] = An0; S->sA[r1][j] = An1;
        __syncthreads();

        // ---------------- Phase 5: action = A_new @ phi + b ----------------
        if (tid < 32) {
            int rr = tid >> 2, o = tid & 3;
            float acc = S->b_phi[o];
#pragma unroll
            for (int k = 0; k < 64; k++)
                acc = fmaf(S->sA[rr][k], S->phi[k][o], acc);
            out[(base + rr) * (TT * 4) + t * 4 + o] = acc;
        }
        // next-iter xs write is ordered by the sync after staging; no hazard
    }
}

extern "C" void kernel_launch(void* const* d_in, const int* in_sizes, int n_in,
                              void* d_out, int out_size) {
    (void)in_sizes; (void)n_in; (void)out_size;
    const size_t shmem = sizeof(SmemLayout);
    cudaFuncSetAttribute(anima_kernel,
                         cudaFuncAttributeMaxDynamicSharedMemorySize,
                         (int)shmem);
    anima_kernel<<<NCTA, NTHREADS, shmem>>>(
        (const float*)d_in[0],
        (const float*)d_in[1], (const float*)d_in[2],
        (const float*)d_in[3], (const float*)d_in[4], (const float*)d_in[5],
        (const float*)d_in[6], (const float*)d_in[7],
        (const float*)d_in[8], (const float*)d_in[9],
        (const float*)d_in[10], (const float*)d_in[11],
        (const float*)d_in[12], (const float*)d_in[13],
        (const float*)d_in[14], (const float*)d_in[15], (const float*)d_in[16],
        (const float*)d_in[17], (const float*)d_in[18],
        (const float*)d_in[19], (const float*)d_in[20],
        (float*)d_out);
}

// round 3
// speedup vs baseline: 1.5460x; 1.5460x over previous
#include <cuda_runtime.h>
#include <cuda_fp16.h>

#define DD 64
#define TT 512
#define BBATCH 1024
#define ROWS_PER_CTA 8
#define NCTA (BBATCH / ROWS_PER_CTA)   /* 128 */
#define NTHREADS 256

// All weights live in SMEM as fp16 (k-interleaved half2), states fp32.
struct SmemLayout {
    __half2 Wff[3][32][64];   // W_from_W, W_from_I, W_from_A
    __half2 Wg[2][32][64];    // W_gate rows [I | A]
    __half2 Iz[3][32][64];    // I_z rows [Wn | I | A]
    __half2 Ir[3][32][64];
    __half2 Ih[3][32][64];    // h rows [Wn | r*I | A]
    __half2 Aff[3][32][64];   // A_from_W, A_from_I, A_from_A
    __half2 Agt[2][32][64];   // A_gate rows [Wn | In]
    float   w_enc[8][64];
    float   phi[64][4];
    float   b_enc[64], b_Wg[64], b_z[64], b_r[64], b_h[64], b_Ag[64], b_phi[4];
    float   sW[8][64], sI[8][64], sA[8][64], sRI[8][64];
    float   xs[8][8];
};

extern __shared__ char smem_raw[];

__device__ __forceinline__ float tanh_f(float x) {
    // accurate tanh via __expf (~1e-6 rel err); clamp avoids inf/inf
    x = fminf(fmaxf(x, -9.0f), 9.0f);
    float e = __expf(2.0f * x);
    return __fdividef(e - 1.0f, e + 1.0f);
}
__device__ __forceinline__ float sigm_f(float x) {
    return __fdividef(1.0f, 1.0f + __expf(-x));
}

// dot over K=64 for two rows sharing the same weight column j.
// w[p][j] holds (wt[2p][j], wt[2p+1][j]); state read as broadcast float4.
__device__ __forceinline__ float2 dot64_pair(const __half2 (&w)[32][64], int j,
                                             const float* __restrict__ s0,
                                             const float* __restrict__ s1) {
    float a0 = 0.f, b0 = 0.f, a1 = 0.f, b1 = 0.f;
#pragma unroll
    for (int q = 0; q < 16; q++) {
        float4 v0 = *reinterpret_cast<const float4*>(s0 + 4 * q);
        float4 v1 = *reinterpret_cast<const float4*>(s1 + 4 * q);
        float2 wa = __half22float2(w[2 * q][j]);
        float2 wb = __half22float2(w[2 * q + 1][j]);
        a0 = fmaf(v0.x, wa.x, a0); b0 = fmaf(v0.y, wa.y, b0);
        a0 = fmaf(v0.z, wb.x, a0); b0 = fmaf(v0.w, wb.y, b0);
        a1 = fmaf(v1.x, wa.x, a1); b1 = fmaf(v1.y, wa.y, b1);
        a1 = fmaf(v1.z, wb.x, a1); b1 = fmaf(v1.w, wb.y, b1);
    }
    return make_float2(a0 + b0, a1 + b1);
}

__device__ __forceinline__ void stage_chunk(__half2 (&dst)[32][64],
                                            const float* __restrict__ src) {
    for (int i = threadIdx.x; i < 2048; i += NTHREADS) {
        int p = i >> 6, jj = i & 63;
        dst[p][jj] = __floats2half2_rn(src[(2 * p) * 64 + jj],
                                       src[(2 * p + 1) * 64 + jj]);
    }
}

__global__ void __launch_bounds__(NTHREADS, 1)
anima_kernel(const float* __restrict__ x,
             const float* __restrict__ we_w, const float* __restrict__ we_b,
             const float* __restrict__ WfW, const float* __restrict__ WfI,
             const float* __restrict__ WfA,
             const float* __restrict__ Wg_w, const float* __restrict__ Wg_b,
             const float* __restrict__ Iz_w, const float* __restrict__ Iz_b,
             const float* __restrict__ Ir_w, const float* __restrict__ Ir_b,
             const float* __restrict__ Ih_w, const float* __restrict__ Ih_b,
             const float* __restrict__ AfW, const float* __restrict__ AfI,
             const float* __restrict__ AfA,
             const float* __restrict__ Ag_w, const float* __restrict__ Ag_b,
             const float* __restrict__ phi_w, const float* __restrict__ phi_b,
             float* __restrict__ out) {
    SmemLayout* S = reinterpret_cast<SmemLayout*>(smem_raw);
    const int tid = threadIdx.x;

    // ---- one-time weight staging (fp32 global -> fp16 smem, k-interleaved)
    stage_chunk(S->Wff[0], WfW);
    stage_chunk(S->Wff[1], WfI);
    stage_chunk(S->Wff[2], WfA);
    stage_chunk(S->Wg[0], Wg_w);
    stage_chunk(S->Wg[1], Wg_w + 64 * 64);
    stage_chunk(S->Iz[0], Iz_w);
    stage_chunk(S->Iz[1], Iz_w + 64 * 64);
    stage_chunk(S->Iz[2], Iz_w + 128 * 64);
    stage_chunk(S->Ir[0], Ir_w);
    stage_chunk(S->Ir[1], Ir_w + 64 * 64);
    stage_chunk(S->Ir[2], Ir_w + 128 * 64);
    stage_chunk(S->Ih[0], Ih_w);
    stage_chunk(S->Ih[1], Ih_w + 64 * 64);
    stage_chunk(S->Ih[2], Ih_w + 128 * 64);
    stage_chunk(S->Aff[0], AfW);
    stage_chunk(S->Aff[1], AfI);
    stage_chunk(S->Aff[2], AfA);
    stage_chunk(S->Agt[0], Ag_w);
    stage_chunk(S->Agt[1], Ag_w + 64 * 64);

    for (int i = tid; i < 8 * 64; i += NTHREADS)
        (&S->w_enc[0][0])[i] = we_w[i];
    for (int i = tid; i < 64 * 4; i += NTHREADS)
        (&S->phi[0][0])[i] = phi_w[i];
    for (int i = tid; i < 64; i += NTHREADS) {
        S->b_enc[i] = we_b[i];
        S->b_Wg[i] = Wg_b[i];
        S->b_z[i] = Iz_b[i];
        S->b_r[i] = Ir_b[i];
        S->b_h[i] = Ih_b[i];
        S->b_Ag[i] = Ag_b[i];
    }
    if (tid < 4) S->b_phi[tid] = phi_b[tid];
    for (int i = tid; i < 8 * 64; i += NTHREADS) {
        (&S->sW[0][0])[i] = 0.f;
        (&S->sI[0][0])[i] = 0.f;
        (&S->sA[0][0])[i] = 0.f;
        (&S->sRI[0][0])[i] = 0.f;
    }
    __syncthreads();

    const int j = tid & 63;
    const int g = tid >> 6;      // 0..3
    const int r0 = g, r1 = g + 4;
    const long base = (long)blockIdx.x * ROWS_PER_CTA;

    for (int t = 0; t < TT; t++) {
        // stage x_t for our 8 rows
        if (tid < 64) {
            int rr = tid >> 3, ss = tid & 7;
            S->xs[rr][ss] = x[(base + rr) * (TT * 8) + t * 8 + ss];
        }
        __syncthreads();

        // ---------------- Phase 1: xt, Wg, W_in -> W_new ----------------
        float e0 = S->b_enc[j], e1 = e0;
#pragma unroll
        for (int s = 0; s < 8; s++) {
            float wv = S->w_enc[s][j];
            e0 = fmaf(S->xs[r0][s], wv, e0);
            e1 = fmaf(S->xs[r1][s], wv, e1);
        }
        float xt0 = tanh_f(e0), xt1 = tanh_f(e1);

        float2 d;
        float gi0 = S->b_Wg[j], gi1 = gi0;
        d = dot64_pair(S->Wg[0], j, S->sI[r0], S->sI[r1]); gi0 += d.x; gi1 += d.y;
        d = dot64_pair(S->Wg[1], j, S->sA[r0], S->sA[r1]); gi0 += d.x; gi1 += d.y;
        float wg0 = sigm_f(gi0), wg1 = sigm_f(gi1);

        float wi0 = xt0, wi1 = xt1;
        d = dot64_pair(S->Wff[0], j, S->sW[r0], S->sW[r1]); wi0 += d.x; wi1 += d.y;
        d = dot64_pair(S->Wff[1], j, S->sI[r0], S->sI[r1]); wi0 += d.x; wi1 += d.y;
        d = dot64_pair(S->Wff[2], j, S->sA[r0], S->sA[r1]); wi0 += d.x; wi1 += d.y;
        float Wn0 = tanh_f(wi0) * wg0;
        float Wn1 = tanh_f(wi1) * wg1;

        __syncthreads();
        S->sW[r0][j] = Wn0; S->sW[r1][j] = Wn1;
        __syncthreads();

        // ---------------- Phase 2: z, r, r*I ----------------
        float z0 = S->b_z[j], z1 = z0;
        float q0 = S->b_r[j], q1 = q0;
        d = dot64_pair(S->Iz[0], j, S->sW[r0], S->sW[r1]); z0 += d.x; z1 += d.y;
        d = dot64_pair(S->Iz[1], j, S->sI[r0], S->sI[r1]); z0 += d.x; z1 += d.y;
        d = dot64_pair(S->Iz[2], j, S->sA[r0], S->sA[r1]); z0 += d.x; z1 += d.y;
        d = dot64_pair(S->Ir[0], j, S->sW[r0], S->sW[r1]); q0 += d.x; q1 += d.y;
        d = dot64_pair(S->Ir[1], j, S->sI[r0], S->sI[r1]); q0 += d.x; q1 += d.y;
        d = dot64_pair(S->Ir[2], j, S->sA[r0], S->sA[r1]); q0 += d.x; q1 += d.y;
        z0 = sigm_f(z0); z1 = sigm_f(z1);
        float rv0 = sigm_f(q0), rv1 = sigm_f(q1);
        float Iold0 = S->sI[r0][j], Iold1 = S->sI[r1][j];
        __syncthreads();
        S->sRI[r0][j] = rv0 * Iold0; S->sRI[r1][j] = rv1 * Iold1;
        __syncthreads();

        // ---------------- Phase 3: h, I_new ----------------
        float h0 = S->b_h[j], h1 = h0;
        d = dot64_pair(S->Ih[0], j, S->sW[r0], S->sW[r1]); h0 += d.x; h1 += d.y;
        d = dot64_pair(S->Ih[1], j, S->sRI[r0], S->sRI[r1]); h0 += d.x; h1 += d.y;
        d = dot64_pair(S->Ih[2], j, S->sA[r0], S->sA[r1]); h0 += d.x; h1 += d.y;
        h0 = tanh_f(h0); h1 = tanh_f(h1);
        float In0 = (1.f - z0) * Iold0 + z0 * h0;
        float In1 = (1.f - z1) * Iold1 + z1 * h1;
        __syncthreads();
        S->sI[r0][j] = In0; S->sI[r1][j] = In1;
        __syncthreads();

        // ---------------- Phase 4: Ag, A_in -> A_new ----------------
        float ga0 = S->b_Ag[j], ga1 = ga0;
        d = dot64_pair(S->Agt[0], j, S->sW[r0], S->sW[r1]); ga0 += d.x; ga1 += d.y;
        d = dot64_pair(S->Agt[1], j, S->sI[r0], S->sI[r1]); ga0 += d.x; ga1 += d.y;
        float ai0 = 0.f, ai1 = 0.f;
        d = dot64_pair(S->Aff[0], j, S->sW[r0], S->sW[r1]); ai0 += d.x; ai1 += d.y;
        d = dot64_pair(S->Aff[1], j, S->sI[r0], S->sI[r1]); ai0 += d.x; ai1 += d.y;
        d = dot64_pair(S->Aff[2], j, S->sA[r0], S->sA[r1]); ai0 += d.x; ai1 += d.y;
        float An0 = tanh_f(ai0) * sigm_f(ga0);
        float An1 = tanh_f(ai1) * sigm_f(ga1);
        __syncthreads();
        S->sA[r0][j] = An0; S->sA[r1][j] = An1;
        __syncthreads();

        // ---------------- Phase 5: action = A_new @ phi + b ----------------
        if (tid < 32) {
            int rr = tid >> 2, o = tid & 3;
            float acc = S->b_phi[o];
#pragma unroll
            for (int k = 0; k < 64; k++)
                acc = fmaf(S->sA[rr][k], S->phi[k][o], acc);
            out[(base + rr) * (TT * 4) + t * 4 + o] = acc;
        }
        // next-iter xs write is ordered by the sync after staging; no hazard
    }
}

extern "C" void kernel_launch(void* const* d_in, const int* in_sizes, int n_in,
                              void* d_out, int out_size) {
    (void)in_sizes; (void)n_in; (void)out_size;
    const size_t shmem = sizeof(SmemLayout);
    cudaFuncSetAttribute(anima_kernel,
                         cudaFuncAttributeMaxDynamicSharedMemorySize,
                         (int)shmem);
    anima_kernel<<<NCTA, NTHREADS, shmem>>>(
        (const float*)d_in[0],
        (const float*)d_in[1], (const float*)d_in[2],
        (const float*)d_in[3], (const float*)d_in[4], (const float*)d_in[5],
        (const float*)d_in[6], (const float*)d_in[7],
        (const float*)d_in[8], (const float*)d_in[9],
        (const float*)d_in[10], (const float*)d_in[11],
        (const float*)d_in[12], (const float*)d_in[13],
        (const float*)d_in[14], (const float*)d_in[15], (const float*)d_in[16],
        (const float*)d_in[17], (const float*)d_in[18],
        (const float*)d_in[19], (const float*)d_in[20],
        (float*)d_out);
}

// round 4
// speedup vs baseline: 2.9165x; 1.8865x over previous
#include <cuda_runtime.h>
#include <cuda_fp16.h>

#define TT 512
#define SDIM 8
#define ODIM 4
#define NTHREADS 256
#define NCTA 128
#define ROWS 8

typedef unsigned long long ull;

// Weights: fp16, packed as uint2 "quads": dst[q][j] holds half2(k=4q,4q+1), half2(k=4q+2,4q+3)
struct __align__(16) Smem {
    uint2 Wff[3][16][64];   // W_from_W, W_from_I, W_from_A
    uint2 Wg[2][16][64];    // W_gate rows [I | A]
    uint2 Iz[3][16][64];    // I_z rows [Wn | I | A]
    uint2 Ir[3][16][64];
    uint2 Ih[3][16][64];    // rows [Wn | r*I | A]
    uint2 Aff[3][16][64];   // A_from_W, A_from_I, A_from_A
    uint2 Agt[2][16][64];   // A_gate rows [Wn | In]
    float sW[2][ROWS][64];  // double-buffered states
    float sI[2][ROWS][64];
    float sA[2][ROWS][64];
    float sRI[ROWS][64];
    float xs[ROWS][SDIM];
};

extern __shared__ char smem_raw[];

__device__ __forceinline__ float tanh_f(float x) {
    x = fminf(fmaxf(x, -9.0f), 9.0f);
    float e = __expf(2.0f * x);
    return __fdividef(e - 1.0f, e + 1.0f);
}
__device__ __forceinline__ float sigm_f(float x) {
    return __fdividef(1.0f, 1.0f + __expf(-x));
}

// half2 (k0,k1) -> packed f32x2 in a b64 register
__device__ __forceinline__ ull h2f2(unsigned int h) {
    ull r;
    asm("{\n\t"
        ".reg .b16 l16, h16;\n\t"
        ".reg .f32 fl, fh;\n\t"
        "mov.b32 {l16, h16}, %1;\n\t"
        "cvt.f32.f16 fl, l16;\n\t"
        "cvt.f32.f16 fh, h16;\n\t"
        "mov.b64 %0, {fl, fh};\n\t"
        "}" : "=l"(r) : "r"(h));
    return r;
}
// d (f32x2) += a * b, both lanes
__device__ __forceinline__ void fma2(ull& d, ull a, ull b) {
    asm("fma.rn.f32x2 %0, %1, %2, %0;" : "+l"(d) : "l"(a), "l"(b));
}
__device__ __forceinline__ float hsum2(ull a, ull b) {
    float ax, ay, bx, by;
    asm("mov.b64 {%0, %1}, %2;" : "=f"(ax), "=f"(ay) : "l"(a));
    asm("mov.b64 {%0, %1}, %2;" : "=f"(bx), "=f"(by) : "l"(b));
    return (ax + bx) + (ay + by);
}

__device__ __forceinline__ void stage4(uint2 (&dst)[16][64],
                                       const float* __restrict__ src) {
#pragma unroll 1
    for (int i = threadIdx.x; i < 1024; i += NTHREADS) {
        int q = i >> 6, jj = i & 63;
        __half2 a = __floats2half2_rn(src[(4 * q + 0) * 64 + jj],
                                      src[(4 * q + 1) * 64 + jj]);
        __half2 b = __floats2half2_rn(src[(4 * q + 2) * 64 + jj],
                                      src[(4 * q + 3) * 64 + jj]);
        uint2 v;
        v.x = *reinterpret_cast<unsigned int*>(&a);
        v.y = *reinterpret_cast<unsigned int*>(&b);
        dst[q][jj] = v;
    }
}

__global__ void __launch_bounds__(NTHREADS, 1)
anima_kernel(const float* __restrict__ x,
             const float* __restrict__ we_w, const float* __restrict__ we_b,
             const float* __restrict__ WfW, const float* __restrict__ WfI,
             const float* __restrict__ WfA,
             const float* __restrict__ Wg_w, const float* __restrict__ Wg_b,
             const float* __restrict__ Iz_w, const float* __restrict__ Iz_b,
             const float* __restrict__ Ir_w, const float* __restrict__ Ir_b,
             const float* __restrict__ Ih_w, const float* __restrict__ Ih_b,
             const float* __restrict__ AfW, const float* __restrict__ AfI,
             const float* __restrict__ AfA,
             const float* __restrict__ Ag_w, const float* __restrict__ Ag_b,
             const float* __restrict__ phi_w, const float* __restrict__ phi_b,
             float* __restrict__ out) {
    Smem* S = reinterpret_cast<Smem*>(smem_raw);
    const int tid = threadIdx.x;

    // ---- one-time staging: fp32 global -> fp16 quads in smem
    stage4(S->Wff[0], WfW);
    stage4(S->Wff[1], WfI);
    stage4(S->Wff[2], WfA);
    stage4(S->Wg[0], Wg_w);
    stage4(S->Wg[1], Wg_w + 64 * 64);
    stage4(S->Iz[0], Iz_w);
    stage4(S->Iz[1], Iz_w + 64 * 64);
    stage4(S->Iz[2], Iz_w + 128 * 64);
    stage4(S->Ir[0], Ir_w);
    stage4(S->Ir[1], Ir_w + 64 * 64);
    stage4(S->Ir[2], Ir_w + 128 * 64);
    stage4(S->Ih[0], Ih_w);
    stage4(S->Ih[1], Ih_w + 64 * 64);
    stage4(S->Ih[2], Ih_w + 128 * 64);
    stage4(S->Aff[0], AfW);
    stage4(S->Aff[1], AfI);
    stage4(S->Aff[2], AfA);
    stage4(S->Agt[0], Ag_w);
    stage4(S->Agt[1], Ag_w + 64 * 64);

#pragma unroll 1
    for (int i = tid; i < 2 * ROWS * 64; i += NTHREADS) {
        (&S->sW[0][0][0])[i] = 0.f;
        (&S->sI[0][0][0])[i] = 0.f;
        (&S->sA[0][0][0])[i] = 0.f;
    }

    // ---- per-thread register constants
    const int j = tid & 63;
    const int g = tid >> 6;      // 0..3
    const int r0 = g, r1 = g + 4;
    const long base = (long)blockIdx.x * ROWS;

    float we[8];
#pragma unroll
    for (int s = 0; s < 8; s++) we[s] = we_w[s * 64 + j];
    const float be = we_b[j], bg = Wg_b[j], bz = Iz_b[j],
                br = Ir_b[j], bh = Ih_b[j], ba = Ag_b[j];

    // Phase-5 mapping: warp = row, lane -> (o, k-segment)
    const int lane = tid & 31, wrow = tid >> 5;
    const int o5 = lane & 3, seg = lane >> 2;
    float ph[8];
#pragma unroll
    for (int kk = 0; kk < 8; kk++) ph[kk] = phi_w[(seg * 8 + kk) * 4 + o5];
    const float bphi = phi_b[o5];

    // x prefetch
    const int xr = tid >> 3, xc = tid & 7;
    const float* xptr = x + (base + xr) * (TT * SDIM) + xc;
    float xv = (tid < 64) ? xptr[0] : 0.f;

    __syncthreads();

    for (int t = 0; t < TT; t++) {
        const int nb = t & 1, pb = nb ^ 1;
        if (tid < 64) S->xs[xr][xc] = xv;
        __syncthreads();
        if (tid < 64 && t + 1 < TT) xv = xptr[(t + 1) * SDIM];

        const ulonglong2* pw0 = (const ulonglong2*)S->sW[pb][r0];
        const ulonglong2* pw1 = (const ulonglong2*)S->sW[pb][r1];
        const ulonglong2* pi0 = (const ulonglong2*)S->sI[pb][r0];
        const ulonglong2* pi1 = (const ulonglong2*)S->sI[pb][r1];
        const ulonglong2* pa0 = (const ulonglong2*)S->sA[pb][r0];
        const ulonglong2* pa1 = (const ulonglong2*)S->sA[pb][r1];

        // ---------- Phase 1: encoder + W gate + W_in ----------
        float e0 = be, e1 = be;
#pragma unroll
        for (int s = 0; s < 8; s++) {
            e0 = fmaf(S->xs[r0][s], we[s], e0);
            e1 = fmaf(S->xs[r1][s], we[s], e1);
        }
        float Wn0, Wn1;
        {
            ull wP0 = 0, wQ0 = 0, wP1 = 0, wQ1 = 0;
            ull gP0 = 0, gQ0 = 0, gP1 = 0, gQ1 = 0;
#pragma unroll 4
            for (int q = 0; q < 16; q++) {
                ulonglong2 w0 = pw0[q], w1 = pw1[q];
                ulonglong2 i0 = pi0[q], i1 = pi1[q];
                ulonglong2 a0 = pa0[q], a1 = pa1[q];
                uint2 m0 = S->Wff[0][q][j]; ull m0x = h2f2(m0.x), m0y = h2f2(m0.y);
                uint2 m1 = S->Wff[1][q][j]; ull m1x = h2f2(m1.x), m1y = h2f2(m1.y);
                uint2 m2 = S->Wff[2][q][j]; ull m2x = h2f2(m2.x), m2y = h2f2(m2.y);
                uint2 u0 = S->Wg[0][q][j];  ull u0x = h2f2(u0.x), u0y = h2f2(u0.y);
                uint2 u1 = S->Wg[1][q][j];  ull u1x = h2f2(u1.x), u1y = h2f2(u1.y);
                fma2(wP0, m0x, w0.x); fma2(wQ0, m0y, w0.y);
                fma2(wP1, m0x, w1.x); fma2(wQ1, m0y, w1.y);
                fma2(gP0, u0x, i0.x); fma2(gQ0, u0y, i0.y);
                fma2(gP1, u0x, i1.x); fma2(gQ1, u0y, i1.y);
                fma2(wP0, m1x, i0.x); fma2(wQ0, m1y, i0.y);
                fma2(wP1, m1x, i1.x); fma2(wQ1, m1y, i1.y);
                fma2(gP0, u1x, a0.x); fma2(gQ0, u1y, a0.y);
                fma2(gP1, u1x, a1.x); fma2(gQ1, u1y, a1.y);
                fma2(wP0, m2x, a0.x); fma2(wQ0, m2y, a0.y);
                fma2(wP1, m2x, a1.x); fma2(wQ1, m2y, a1.y);
            }
            float xt0 = tanh_f(e0), xt1 = tanh_f(e1);
            Wn0 = tanh_f(xt0 + hsum2(wP0, wQ0)) * sigm_f(bg + hsum2(gP0, gQ0));
            Wn1 = tanh_f(xt1 + hsum2(wP1, wQ1)) * sigm_f(bg + hsum2(gP1, gQ1));
        }
        S->sW[nb][r0][j] = Wn0;
        S->sW[nb][r1][j] = Wn1;
        __syncthreads();

        const ulonglong2* nw0 = (const ulonglong2*)S->sW[nb][r0];
        const ulonglong2* nw1 = (const ulonglong2*)S->sW[nb][r1];

        // ---------- Phase 2: z, r gates; stash r*I ----------
        float z_0, z_1, Iold0, Iold1;
        {
            ull zP0 = 0, zQ0 = 0, zP1 = 0, zQ1 = 0;
            ull rP0 = 0, rQ0 = 0, rP1 = 0, rQ1 = 0;
#pragma unroll 4
            for (int q = 0; q < 16; q++) {
                ulonglong2 w0 = nw0[q], w1 = nw1[q];
                ulonglong2 i0 = pi0[q], i1 = pi1[q];
                ulonglong2 a0 = pa0[q], a1 = pa1[q];
                uint2 za = S->Iz[0][q][j]; ull zax = h2f2(za.x), zay = h2f2(za.y);
                uint2 zb = S->Iz[1][q][j]; ull zbx = h2f2(zb.x), zby = h2f2(zb.y);
                uint2 zc = S->Iz[2][q][j]; ull zcx = h2f2(zc.x), zcy = h2f2(zc.y);
                uint2 ra = S->Ir[0][q][j]; ull rax = h2f2(ra.x), ray = h2f2(ra.y);
                uint2 rb = S->Ir[1][q][j]; ull rbx = h2f2(rb.x), rby = h2f2(rb.y);
                uint2 rc = S->Ir[2][q][j]; ull rcx = h2f2(rc.x), rcy = h2f2(rc.y);
                fma2(zP0, zax, w0.x); fma2(zQ0, zay, w0.y);
                fma2(zP1, zax, w1.x); fma2(zQ1, zay, w1.y);
                fma2(rP0, rax, w0.x); fma2(rQ0, ray, w0.y);
                fma2(rP1, rax, w1.x); fma2(rQ1, ray, w1.y);
                fma2(zP0, zbx, i0.x); fma2(zQ0, zby, i0.y);
                fma2(zP1, zbx, i1.x); fma2(zQ1, zby, i1.y);
                fma2(rP0, rbx, i0.x); fma2(rQ0, rby, i0.y);
                fma2(rP1, rbx, i1.x); fma2(rQ1, rby, i1.y);
                fma2(zP0, zcx, a0.x); fma2(zQ0, zcy, a0.y);
                fma2(zP1, zcx, a1.x); fma2(zQ1, zcy, a1.y);
                fma2(rP0, rcx, a0.x); fma2(rQ0, rcy, a0.y);
                fma2(rP1, rcx, a1.x); fma2(rQ1, rcy, a1.y);
            }
            z_0 = sigm_f(bz + hsum2(zP0, zQ0));
            z_1 = sigm_f(bz + hsum2(zP1, zQ1));
            float rv0 = sigm_f(br + hsum2(rP0, rQ0));
            float rv1 = sigm_f(br + hsum2(rP1, rQ1));
            Iold0 = S->sI[pb][r0][j];
            Iold1 = S->sI[pb][r1][j];
            S->sRI[r0][j] = rv0 * Iold0;
            S->sRI[r1][j] = rv1 * Iold1;
        }
        __syncthreads();

        // ---------- Phase 3: h, I_new ----------
        float In0, In1;
        {
            const ulonglong2* q0p = (const ulonglong2*)S->sRI[r0];
            const ulonglong2* q1p = (const ulonglong2*)S->sRI[r1];
            ull hP0 = 0, hQ0 = 0, hP1 = 0, hQ1 = 0;
#pragma unroll 8
            for (int q = 0; q < 16; q++) {
                ulonglong2 w0 = nw0[q], w1 = nw1[q];
                ulonglong2 i0 = q0p[q], i1 = q1p[q];
                ulonglong2 a0 = pa0[q], a1 = pa1[q];
                uint2 ha = S->Ih[0][q][j]; ull hax = h2f2(ha.x), hay = h2f2(ha.y);
                uint2 hb = S->Ih[1][q][j]; ull hbx = h2f2(hb.x), hby = h2f2(hb.y);
                uint2 hc = S->Ih[2][q][j]; ull hcx = h2f2(hc.x), hcy = h2f2(hc.y);
                fma2(hP0, hax, w0.x); fma2(hQ0, hay, w0.y);
                fma2(hP1, hax, w1.x); fma2(hQ1, hay, w1.y);
                fma2(hP0, hbx, i0.x); fma2(hQ0, hby, i0.y);
                fma2(hP1, hbx, i1.x); fma2(hQ1, hby, i1.y);
                fma2(hP0, hcx, a0.x); fma2(hQ0, hcy, a0.y);
                fma2(hP1, hcx, a1.x); fma2(hQ1, hcy, a1.y);
            }
            float h0 = tanh_f(bh + hsum2(hP0, hQ0));
            float h1 = tanh_f(bh + hsum2(hP1, hQ1));
            In0 = (1.f - z_0) * Iold0 + z_0 * h0;
            In1 = (1.f - z_1) * Iold1 + z_1 * h1;
        }
        S->sI[nb][r0][j] = In0;
        S->sI[nb][r1][j] = In1;
        __syncthreads();

        // ---------- Phase 4: A gate + A_in -> A_new ----------
        {
            const ulonglong2* ni0 = (const ulonglong2*)S->sI[nb][r0];
            const ulonglong2* ni1 = (const ulonglong2*)S->sI[nb][r1];
            ull aP0 = 0, aQ0 = 0, aP1 = 0, aQ1 = 0;
            ull cP0 = 0, cQ0 = 0, cP1 = 0, cQ1 = 0;
#pragma unroll 4
            for (int q = 0; q < 16; q++) {
                ulonglong2 w0 = nw0[q], w1 = nw1[q];
                ulonglong2 i0 = ni0[q], i1 = ni1[q];
                ulonglong2 a0 = pa0[q], a1 = pa1[q];
                uint2 fa = S->Aff[0][q][j]; ull fax = h2f2(fa.x), fay = h2f2(fa.y);
                uint2 fb = S->Aff[1][q][j]; ull fbx = h2f2(fb.x), fby = h2f2(fb.y);
                uint2 fc = S->Aff[2][q][j]; ull fcx = h2f2(fc.x), fcy = h2f2(fc.y);
                uint2 ga = S->Agt[0][q][j]; ull gax = h2f2(ga.x), gay = h2f2(ga.y);
                uint2 gb = S->Agt[1][q][j]; ull gbx = h2f2(gb.x), gby = h2f2(gb.y);
                fma2(aP0, fax, w0.x); fma2(aQ0, fay, w0.y);
                fma2(aP1, fax, w1.x); fma2(aQ1, fay, w1.y);
                fma2(cP0, gax, w0.x); fma2(cQ0, gay, w0.y);
                fma2(cP1, gax, w1.x); fma2(cQ1, gay, w1.y);
                fma2(aP0, fbx, i0.x); fma2(aQ0, fby, i0.y);
                fma2(aP1, fbx, i1.x); fma2(aQ1, fby, i1.y);
                fma2(cP0, gbx, i0.x); fma2(cQ0, gby, i0.y);
                fma2(cP1, gbx, i1.x); fma2(cQ1, gby, i1.y);
                fma2(aP0, fcx, a0.x); fma2(aQ0, fcy, a0.y);
                fma2(aP1, fcx, a1.x); fma2(aQ1, fcy, a1.y);
            }
            float An0 = tanh_f(hsum2(aP0, aQ0)) * sigm_f(ba + hsum2(cP0, cQ0));
            float An1 = tanh_f(hsum2(aP1, aQ1)) * sigm_f(ba + hsum2(cP1, cQ1));
            S->sA[nb][r0][j] = An0;
            S->sA[nb][r1][j] = An1;
        }
        __syncthreads();

        // ---------- Phase 5: action = A_new @ phi + b (warp = row) ----------
        {
            const float4* par = (const float4*)S->sA[nb][wrow];
            float4 v0 = par[seg * 2], v1 = par[seg * 2 + 1];
            float p = v0.x * ph[0];
            p = fmaf(v0.y, ph[1], p);
            p = fmaf(v0.z, ph[2], p);
            p = fmaf(v0.w, ph[3], p);
            p = fmaf(v1.x, ph[4], p);
            p = fmaf(v1.y, ph[5], p);
            p = fmaf(v1.z, ph[6], p);
            p = fmaf(v1.w, ph[7], p);
            p += __shfl_down_sync(0xffffffffu, p, 16);
            p += __shfl_down_sync(0xffffffffu, p, 8);
            p += __shfl_down_sync(0xffffffffu, p, 4);
            if (lane < 4)
                out[(base + wrow) * (TT * ODIM) + t * ODIM + o5] = p + bphi;
        }
        // next-iteration xs write is guarded by the loop-top __syncthreads
    }
}

extern "C" void kernel_launch(void* const* d_in, const int* in_sizes, int n_in,
                              void* d_out, int out_size) {
    (void)in_sizes; (void)n_in; (void)out_size;
    const size_t shmem = sizeof(Smem);
    cudaFuncSetAttribute(anima_kernel,
                         cudaFuncAttributeMaxDynamicSharedMemorySize,
                         (int)shmem);
    anima_kernel<<<NCTA, NTHREADS, shmem>>>(
        (const float*)d_in[0],
        (const float*)d_in[1], (const float*)d_in[2],
        (const float*)d_in[3], (const float*)d_in[4], (const float*)d_in[5],
        (const float*)d_in[6], (const float*)d_in[7],
        (const float*)d_in[8], (const float*)d_in[9],
        (const float*)d_in[10], (const float*)d_in[11],
        (const float*)d_in[12], (const float*)d_in[13],
        (const float*)d_in[14], (const float*)d_in[15], (const float*)d_in[16],
        (const float*)d_in[17], (const float*)d_in[18],
        (const float*)d_in[19], (const float*)d_in[20],
        (float*)d_out);
}

// round 7
// speedup vs baseline: 3.3503x; 1.1487x over previous
#include <cuda_runtime.h>
#include <cuda_fp16.h>

#define TT 512
#define SDIM 8
#define ODIM 4
#define NTHREADS 256
#define NCTA 128
#define ROWS 8
#define ROWF 72   // 64 state floats + 16B skew between k-halves + pad

typedef unsigned long long ull;

// Weights: fp16 quads: arr[q][j] = {half2(k=4q,4q+1), half2(k=4q+2,4q+3)}
struct __align__(16) Smem {
    uint2 Wff[3][16][64];   // W_from_W, W_from_I, W_from_A
    uint2 Wg[2][16][64];    // W_gate rows [I | A]
    uint2 Iz[3][16][64];
    uint2 Ir[3][16][64];
    uint2 Ih[3][16][64];    // rows [Wn | r*I | A]
    uint2 Aff[3][16][64];
    uint2 Agt[2][16][64];   // rows [Wn | In]
    float sW[2][ROWS][ROWF];  // double-buffered states, skewed rows
    float sI[2][ROWS][ROWF];
    float sA[2][ROWS][ROWF];
    float sRI[ROWS][ROWF];
    float xs[ROWS][SDIM];
};

extern __shared__ char smem_raw[];

__device__ __forceinline__ float tanh_f(float x) {
    x = fminf(fmaxf(x, -9.0f), 9.0f);
    float e = __expf(2.0f * x);
    return __fdividef(e - 1.0f, e + 1.0f);
}
__device__ __forceinline__ float sigm_f(float x) {
    return __fdividef(1.0f, 1.0f + __expf(-x));
}

__device__ __forceinline__ ull h2f2(unsigned int h) {
    ull r;
    asm("{\n\t"
        ".reg .b16 l16, h16;\n\t"
        ".reg .f32 fl, fh;\n\t"
        "mov.b32 {l16, h16}, %1;\n\t"
        "cvt.f32.f16 fl, l16;\n\t"
        "cvt.f32.f16 fh, h16;\n\t"
        "mov.b64 %0, {fl, fh};\n\t"
        "}" : "=l"(r) : "r"(h));
    return r;
}
__device__ __forceinline__ void fma2(ull& d, ull a, ull b) {
    asm("fma.rn.f32x2 %0, %1, %2, %0;" : "+l"(d) : "l"(a), "l"(b));
}
__device__ __forceinline__ float hsum2(ull a, ull b) {
    float ax, ay, bx, by;
    asm("mov.b64 {%0, %1}, %2;" : "=f"(ax), "=f"(ay) : "l"(a));
    asm("mov.b64 {%0, %1}, %2;" : "=f"(bx), "=f"(by) : "l"(b));
    return (ax + bx) + (ay + by);
}
// k-half partial -> full dot (partner lane is lane^16)
__device__ __forceinline__ float red32(ull P, ull Q) {
    float p = hsum2(P, Q);
    return p + __shfl_xor_sync(0xffffffffu, p, 16);
}

__device__ __forceinline__ void stage4(uint2 (&dst)[16][64],
                                       const float* __restrict__ src) {
#pragma unroll 1
    for (int i = threadIdx.x; i < 1024; i += NTHREADS) {
        int q = i >> 6, jj = i & 63;
        __half2 a = __floats2half2_rn(src[(4 * q + 0) * 64 + jj],
                                      src[(4 * q + 1) * 64 + jj]);
        __half2 b = __floats2half2_rn(src[(4 * q + 2) * 64 + jj],
                                      src[(4 * q + 3) * 64 + jj]);
        uint2 v;
        v.x = *reinterpret_cast<unsigned int*>(&a);
        v.y = *reinterpret_cast<unsigned int*>(&b);
        dst[q][jj] = v;
    }
}

__global__ void __launch_bounds__(NTHREADS, 1)
anima_kernel(const float* __restrict__ x,
             const float* __restrict__ we_w, const float* __restrict__ we_b,
             const float* __restrict__ WfW, const float* __restrict__ WfI,
             const float* __restrict__ WfA,
             const float* __restrict__ Wg_w, const float* __restrict__ Wg_b,
             const float* __restrict__ Iz_w, const float* __restrict__ Iz_b,
             const float* __restrict__ Ir_w, const float* __restrict__ Ir_b,
             const float* __restrict__ Ih_w, const float* __restrict__ Ih_b,
             const float* __restrict__ AfW, const float* __restrict__ AfI,
             const float* __restrict__ AfA,
             const float* __restrict__ Ag_w, const float* __restrict__ Ag_b,
             const float* __restrict__ phi_w, const float* __restrict__ phi_b,
             float* __restrict__ out) {
    Smem* S = reinterpret_cast<Smem*>(smem_raw);
    const int tid = threadIdx.x;

    // ---- one-time staging
    stage4(S->Wff[0], WfW);
    stage4(S->Wff[1], WfI);
    stage4(S->Wff[2], WfA);
    stage4(S->Wg[0], Wg_w);
    stage4(S->Wg[1], Wg_w + 64 * 64);
    stage4(S->Iz[0], Iz_w);
    stage4(S->Iz[1], Iz_w + 64 * 64);
    stage4(S->Iz[2], Iz_w + 128 * 64);
    stage4(S->Ir[0], Ir_w);
    stage4(S->Ir[1], Ir_w + 64 * 64);
    stage4(S->Ir[2], Ir_w + 128 * 64);
    stage4(S->Ih[0], Ih_w);
    stage4(S->Ih[1], Ih_w + 64 * 64);
    stage4(S->Ih[2], Ih_w + 128 * 64);
    stage4(S->Aff[0], AfW);
    stage4(S->Aff[1], AfI);
    stage4(S->Aff[2], AfA);
    stage4(S->Agt[0], Ag_w);
    stage4(S->Agt[1], Ag_w + 64 * 64);

#pragma unroll 1
    for (int i = tid; i < 2 * ROWS * ROWF; i += NTHREADS) {
        (&S->sW[0][0][0])[i] = 0.f;
        (&S->sI[0][0][0])[i] = 0.f;
        (&S->sA[0][0][0])[i] = 0.f;
    }

    // ---- thread mapping: warp = (rowhalf, jgroup); lane = (khalf, jj)
    const int lane = tid & 31, w = tid >> 5;
    const int jg = w & 3, rh = w >> 2;
    const int jj = lane & 15, kh = lane >> 4;
    const int j = jg * 16 + jj;
    const int js = j + ((j >> 5) << 2);   // skewed in-row offset
    const int R = rh * 4;                 // first of this thread's 4 rows
    const int khq = kh * 8;               // weight quad base
    const int khf = kh * 36;              // state float base (skewed)
    const long base = (long)blockIdx.x * ROWS;

    float we[8];
#pragma unroll
    for (int s = 0; s < 8; s++) we[s] = we_w[s * 64 + j];
    const float be = we_b[j], bg = Wg_b[j], bz = Iz_b[j],
                br = Ir_b[j], bh = Ih_b[j], ba = Ag_b[j];

    // Phase-5 mapping: warp = row, lane -> (o, k-segment)
    const int wrow = w;
    const int o5 = lane & 3, seg = lane >> 2;
    float ph[8];
#pragma unroll
    for (int kk = 0; kk < 8; kk++) ph[kk] = phi_w[(seg * 8 + kk) * 4 + o5];
    const float bphi = phi_b[o5];
    const int segoff = (seg < 4) ? seg * 8 : 36 + (seg - 4) * 8;

    // x prefetch + first staging
    const int xr = tid >> 3, xc = tid & 7;
    const float* xptr = x + (base + xr) * (TT * SDIM) + xc;
    float xv = (tid < 64) ? xptr[0] : 0.f;
    __syncthreads();
    if (tid < 64) S->xs[xr][xc] = xv;
    __syncthreads();

    for (int t = 0; t < TT; t++) {
        const int nb = t & 1, pb = nb ^ 1;
        if (tid < 64 && t + 1 < TT) xv = xptr[(t + 1) * SDIM];

        const ulonglong2 *pw[4], *pi[4], *pa[4];
#pragma unroll
        for (int r = 0; r < 4; r++) {
            pw[r] = (const ulonglong2*)(S->sW[pb][R + r] + khf);
            pi[r] = (const ulonglong2*)(S->sI[pb][R + r] + khf);
            pa[r] = (const ulonglong2*)(S->sA[pb][R + r] + khf);
        }

        // ---------- Phase 1: encoder + W gate + W_in ----------
        float enc[4];
#pragma unroll
        for (int r = 0; r < 4; r++) {
            const float4* x4 = reinterpret_cast<const float4*>(S->xs[R + r]);
            float4 a = x4[0], b = x4[1];
            float e = be;
            e = fmaf(a.x, we[0], e); e = fmaf(a.y, we[1], e);
            e = fmaf(a.z, we[2], e); e = fmaf(a.w, we[3], e);
            e = fmaf(b.x, we[4], e); e = fmaf(b.y, we[5], e);
            e = fmaf(b.z, we[6], e); e = fmaf(b.w, we[7], e);
            enc[r] = tanh_f(e);
        }
        {
            ull aW[4][2] = {}, aG[4][2] = {};
#pragma unroll
            for (int q = 0; q < 8; q++) {
                const int qw = khq + q;
                uint2 m0 = S->Wff[0][qw][j]; ull m0x = h2f2(m0.x), m0y = h2f2(m0.y);
                uint2 m1 = S->Wff[1][qw][j]; ull m1x = h2f2(m1.x), m1y = h2f2(m1.y);
                uint2 m2 = S->Wff[2][qw][j]; ull m2x = h2f2(m2.x), m2y = h2f2(m2.y);
                uint2 u0 = S->Wg[0][qw][j];  ull u0x = h2f2(u0.x), u0y = h2f2(u0.y);
                uint2 u1 = S->Wg[1][qw][j];  ull u1x = h2f2(u1.x), u1y = h2f2(u1.y);
#pragma unroll
                for (int r = 0; r < 4; r++) {
                    ulonglong2 vw = pw[r][q], vi = pi[r][q], va = pa[r][q];
                    fma2(aW[r][0], m0x, vw.x); fma2(aW[r][1], m0y, vw.y);
                    fma2(aW[r][0], m1x, vi.x); fma2(aW[r][1], m1y, vi.y);
                    fma2(aG[r][0], u0x, vi.x); fma2(aG[r][1], u0y, vi.y);
                    fma2(aW[r][0], m2x, va.x); fma2(aW[r][1], m2y, va.y);
                    fma2(aG[r][0], u1x, va.x); fma2(aG[r][1], u1y, va.y);
                }
            }
#pragma unroll
            for (int r = 0; r < 4; r++) {
                float win = red32(aW[r][0], aW[r][1]);
                float gin = red32(aG[r][0], aG[r][1]);
                float Wn = tanh_f(enc[r] + win) * sigm_f(bg + gin);
                if (kh == 0) S->sW[nb][R + r][js] = Wn;
            }
        }
        __syncthreads();

        const ulonglong2* pwn[4];
#pragma unroll
        for (int r = 0; r < 4; r++)
            pwn[r] = (const ulonglong2*)(S->sW[nb][R + r] + khf);

        // ---------- Phase 2: z, r gates; stash r*I ----------
        float zv[4], Iold[4];
        {
            ull aZ[4][2] = {}, aR[4][2] = {};
#pragma unroll
            for (int q = 0; q < 8; q++) {
                const int qw = khq + q;
                uint2 za = S->Iz[0][qw][j]; ull zax = h2f2(za.x), zay = h2f2(za.y);
                uint2 zb = S->Iz[1][qw][j]; ull zbx = h2f2(zb.x), zby = h2f2(zb.y);
                uint2 zc = S->Iz[2][qw][j]; ull zcx = h2f2(zc.x), zcy = h2f2(zc.y);
                uint2 ra = S->Ir[0][qw][j]; ull rax = h2f2(ra.x), ray = h2f2(ra.y);
                uint2 rb = S->Ir[1][qw][j]; ull rbx = h2f2(rb.x), rby = h2f2(rb.y);
                uint2 rc = S->Ir[2][qw][j]; ull rcx = h2f2(rc.x), rcy = h2f2(rc.y);
#pragma unroll
                for (int r = 0; r < 4; r++) {
                    ulonglong2 vw = pwn[r][q], vi = pi[r][q], va = pa[r][q];
                    fma2(aZ[r][0], zax, vw.x); fma2(aZ[r][1], zay, vw.y);
                    fma2(aR[r][0], rax, vw.x); fma2(aR[r][1], ray, vw.y);
                    fma2(aZ[r][0], zbx, vi.x); fma2(aZ[r][1], zby, vi.y);
                    fma2(aR[r][0], rbx, vi.x); fma2(aR[r][1], rby, vi.y);
                    fma2(aZ[r][0], zcx, va.x); fma2(aZ[r][1], zcy, va.y);
                    fma2(aR[r][0], rcx, va.x); fma2(aR[r][1], rcy, va.y);
                }
            }
#pragma unroll
            for (int r = 0; r < 4; r++) {
                zv[r] = sigm_f(bz + red32(aZ[r][0], aZ[r][1]));
                float rv = sigm_f(br + red32(aR[r][0], aR[r][1]));
                Iold[r] = S->sI[pb][R + r][js];
                if (kh == 0) S->sRI[R + r][js] = rv * Iold[r];
            }
        }
        __syncthreads();

        // ---------- Phase 3: h, I_new ----------
        {
            const ulonglong2* pri[4];
#pragma unroll
            for (int r = 0; r < 4; r++)
                pri[r] = (const ulonglong2*)(S->sRI[R + r] + khf);
            ull aH[4][2] = {};
#pragma unroll
            for (int q = 0; q < 8; q++) {
                const int qw = khq + q;
                uint2 ha = S->Ih[0][qw][j]; ull hax = h2f2(ha.x), hay = h2f2(ha.y);
                uint2 hb = S->Ih[1][qw][j]; ull hbx = h2f2(hb.x), hby = h2f2(hb.y);
                uint2 hc = S->Ih[2][qw][j]; ull hcx = h2f2(hc.x), hcy = h2f2(hc.y);
#pragma unroll
                for (int r = 0; r < 4; r++) {
                    ulonglong2 vw = pwn[r][q], vq = pri[r][q], va = pa[r][q];
                    fma2(aH[r][0], hax, vw.x); fma2(aH[r][1], hay, vw.y);
                    fma2(aH[r][0], hbx, vq.x); fma2(aH[r][1], hby, vq.y);
                    fma2(aH[r][0], hcx, va.x); fma2(aH[r][1], hcy, va.y);
                }
            }
#pragma unroll
            for (int r = 0; r < 4; r++) {
                float h = tanh_f(bh + red32(aH[r][0], aH[r][1]));
                float In = (1.f - zv[r]) * Iold[r] + zv[r] * h;
                if (kh == 0) S->sI[nb][R + r][js] = In;
            }
        }
        __syncthreads();

        // ---------- Phase 4: A gate + A_in -> A_new ----------
        {
            const ulonglong2* pin[4];
#pragma unroll
            for (int r = 0; r < 4; r++)
                pin[r] = (const ulonglong2*)(S->sI[nb][R + r] + khf);
            ull aA[4][2] = {}, aC[4][2] = {};
#pragma unroll
            for (int q = 0; q < 8; q++) {
                const int qw = khq + q;
                uint2 fa = S->Aff[0][qw][j]; ull fax = h2f2(fa.x), fay = h2f2(fa.y);
                uint2 fb = S->Aff[1][qw][j]; ull fbx = h2f2(fb.x), fby = h2f2(fb.y);
                uint2 fc = S->Aff[2][qw][j]; ull fcx = h2f2(fc.x), fcy = h2f2(fc.y);
                uint2 ga = S->Agt[0][qw][j]; ull gax = h2f2(ga.x), gay = h2f2(ga.y);
                uint2 gb = S->Agt[1][qw][j]; ull gbx = h2f2(gb.x), gby = h2f2(gb.y);
#pragma unroll
                for (int r = 0; r < 4; r++) {
                    ulonglong2 vw = pwn[r][q], vi = pin[r][q], va = pa[r][q];
                    fma2(aA[r][0], fax, vw.x); fma2(aA[r][1], fay, vw.y);
                    fma2(aC[r][0], gax, vw.x); fma2(aC[r][1], gay, vw.y);
                    fma2(aA[r][0], fbx, vi.x); fma2(aA[r][1], fby, vi.y);
                    fma2(aC[r][0], gbx, vi.x); fma2(aC[r][1], gby, vi.y);
                    fma2(aA[r][0], fcx, va.x); fma2(aA[r][1], fcy, va.y);
                }
            }
#pragma unroll
            for (int r = 0; r < 4; r++) {
                float ain = red32(aA[r][0], aA[r][1]);
                float gin = red32(aC[r][0], aC[r][1]);
                float An = tanh_f(ain) * sigm_f(ba + gin);
                if (kh == 0) S->sA[nb][R + r][js] = An;
            }
        }
        if (tid < 64) S->xs[xr][xc] = xv;   // stage x for t+1
        __syncthreads();

        // ---------- Phase 5: action = A_new @ phi + b (warp = row) ----------
        {
            const float* arow = S->sA[nb][wrow] + segoff;
            float4 v0 = *reinterpret_cast<const float4*>(arow);
            float4 v1 = *reinterpret_cast<const float4*>(arow + 4);
            float p = v0.x * ph[0];
            p = fmaf(v0.y, ph[1], p);
            p = fmaf(v0.z, ph[2], p);
            p = fmaf(v0.w, ph[3], p);
            p = fmaf(v1.x, ph[4], p);
            p = fmaf(v1.y, ph[5], p);
            p = fmaf(v1.z, ph[6], p);
            p = fmaf(v1.w, ph[7], p);
            p += __shfl_down_sync(0xffffffffu, p, 16);
            p += __shfl_down_sync(0xffffffffu, p, 8);
            p += __shfl_down_sync(0xffffffffu, p, 4);
            if (lane < 4)
                out[(base + wrow) * (TT * ODIM) + t * ODIM + o5] = p + bphi;
        }
    }
}

extern "C" void kernel_launch(void* const* d_in, const int* in_sizes, int n_in,
                              void* d_out, int out_size) {
    (void)in_sizes; (void)n_in; (void)out_size;
    const size_t shmem = sizeof(Smem);
    cudaFuncSetAttribute(anima_kernel,
                         cudaFuncAttributeMaxDynamicSharedMemorySize,
                         (int)shmem);
    anima_kernel<<<NCTA, NTHREADS, shmem>>>(
        (const float*)d_in[0],
        (const float*)d_in[1], (const float*)d_in[2],
        (const float*)d_in[3], (const float*)d_in[4], (const float*)d_in[5],
        (const float*)d_in[6], (const float*)d_in[7],
        (const float*)d_in[8], (const float*)d_in[9],
        (const float*)d_in[10], (const float*)d_in[11],
        (const float*)d_in[12], (const float*)d_in[13],
        (const float*)d_in[14], (const float*)d_in[15], (const float*)d_in[16],
        (const float*)d_in[17], (const float*)d_in[18],
        (const float*)d_in[19], (const float*)d_in[20],
        (float*)d_out);
}